// round 15
// baseline (speedup 1.0000x reference)
#include <cuda_runtime.h>

#define WIN       1024
#define NH        64
#define SEGS      8
#define SEGLEN    (WIN / SEGS)      // 128
#define SEGPAIRS  (SEGS / 2)        // 4
#define THREADS   (NH * SEGPAIRS)   // 256

// Packed-f32x2 Goertzel Morlet harmonic transform.
// One block per frame. Thread (k, sp) runs TWO Goertzel recurrences packed in
// f32x2 registers: segment sp (samples sp*128..) in the low lane and segment
// sp+4 (samples 512+sp*128..) in the high lane. Inputs are staged interleaved
// in smem so one LDS.128 feeds two packed steps with zero packing overhead.
// Inner loop: 2 FFMA2 per packed step = 1 fma-pipe inst per harmonic-sample.

#define FMA2(d, a, b, c) \
    asm("fma.rn.f32x2 %0, %1, %2, %3;" \
        : "=l"(d) : "l"(a), "l"(b), "l"(c))

#define PACK2(d, lo, hi) \
    asm("mov.b64 %0, {%1, %2};" : "=l"(d) : "r"(lo), "r"(hi))

#define UNPACK2(lo, hi, s) \
    asm("mov.b64 {%0, %1}, %2;" : "=r"(lo), "=r"(hi) : "l"(s))

__global__ __launch_bounds__(THREADS)
void morlet_kernel(const float* __restrict__ audio,
                   const float* __restrict__ f0,
                   float* __restrict__ out_hd,
                   float* __restrict__ out_amp)
{
    // xw2[2*j] = xw[j], xw2[2*j+1] = xw[j+512]  (j = 0..511)
    __shared__ __align__(16) float xw2[2 * WIN / 2 * 2];  // 2048 floats = 8KB
    __shared__ float pre[SEGS * NH];
    __shared__ float pim[SEGS * NH];
    __shared__ float tk[NH];
    __shared__ float red[2];

    const int frame = blockIdx.x;
    const int tid   = threadIdx.x;

    // normalizer = 1/sqrt(pi * 16000)
    const float normalizer = 0.00446031f;

    // Stage windowed samples interleaved: low half / high half paired.
    const float* x = audio + (size_t)frame * WIN;
    #pragma unroll
    for (int n = tid; n < WIN; n += THREADS) {
        float d = (float)(n - WIN / 2);
        float g = __expf(-d * d * (1.0f / 16000.0f)) * normalizer;
        float v = g * x[n];
        int j   = n & (WIN / 2 - 1);          // n mod 512
        int hi  = n >> 9;                     // 0 = low half, 1 = high half
        xw2[2 * j + hi] = v;
    }
    __syncthreads();

    const int k  = tid & (NH - 1);            // harmonic 0..63 (harmonic k+1)
    const int sp = tid >> 6;                  // segment pair 0..3

    const float kf = (float)(k + 1);
    const float f  = f0[frame];
    const float fc = (f * kf) * (1.0f / 16000.0f);

    float sw, cw;
    sincospif(2.0f * fc, &sw, &cw);
    const float c2 = 2.0f * cw;

    unsigned long long c2p, neg1, s1 = 0ull, s2 = 0ull;
    {
        unsigned int c2b = __float_as_uint(c2);
        unsigned int nb  = __float_as_uint(-1.0f);
        PACK2(c2p, c2b, c2b);
        PACK2(neg1, nb, nb);
    }

    // Dual Goertzel over 128 packed steps (segments sp and sp+4).
    // Each ulonglong2 load covers 2 packed steps.
    const ulonglong2* xv =
        (const ulonglong2*)(xw2 + sp * 2 * SEGLEN);
    #pragma unroll
    for (int i = 0; i < SEGLEN / 2; i++) {
        ulonglong2 w = xv[i];
        unsigned long long t, s;
        FMA2(t, s2, neg1, w.x);   // t = w - s2
        FMA2(s, c2p, s1, t);      // s = c2*s1 + t
        s2 = s1; s1 = s;
        FMA2(t, s2, neg1, w.y);
        FMA2(s, c2p, s1, t);
        s2 = s1; s1 = s;
    }

    // Unpack the two recurrence states.
    unsigned int u1lo, u1hi, u2lo, u2hi;
    UNPACK2(u1lo, u1hi, s1);
    UNPACK2(u2lo, u2hi, s2);

    // Extract + phase-correct both segments.
    #pragma unroll
    for (int h = 0; h < 2; h++) {
        float a1 = __uint_as_float(h ? u1hi : u1lo);
        float a2 = __uint_as_float(h ? u2hi : u2lo);
        int   seg = sp + h * SEGPAIRS;              // sp or sp+4
        float yre = fmaf(-cw, a2, a1);
        float yim = sw * a2;
        int   n_end = seg * SEGLEN + SEGLEN - 1;
        float ph = fc * (float)n_end;
        float fr = ph - floorf(ph);
        float spn, cpn;
        sincospif(-2.0f * fr, &spn, &cpn);
        pre[seg * NH + k] = cpn * yre - spn * yim;
        pim[seg * NH + k] = fmaf(cpn, yim, spn * yre);
    }
    __syncthreads();

    // Combine segment partials (complex sum BEFORE abs), magnitude.
    if (tid < NH) {
        float re = 0.0f, im = 0.0f;
        #pragma unroll
        for (int s = 0; s < SEGS; s++) {
            re += pre[s * NH + tid];
            im += pim[s * NH + tid];
        }
        float t = sqrtf(fmaf(re, re, im * im));
        if (fc > 0.5f) t = 0.0f;   // Nyquist mask (fc of this tid is seg-pair 0)
        tk[tid] = t;
    }
    __syncthreads();

    // Sum over harmonics -> amp_raw
    if (tid < NH) {
        float v = tk[tid];
        #pragma unroll
        for (int o = 16; o > 0; o >>= 1)
            v += __shfl_down_sync(0xffffffffu, v, o);
        if ((tid & 31) == 0) red[tid >> 5] = v;
    }
    __syncthreads();

    const float amp_raw = red[0] + red[1];

    if (tid < NH) {
        out_hd[(size_t)frame * NH + tid] = tk[tid] / amp_raw;
    }
    if (tid == 0) {
        out_amp[frame] = fminf(fmaxf(amp_raw * 2.0f, 0.0f), 1.0f);
    }
}

extern "C" void kernel_launch(void* const* d_in, const int* in_sizes, int n_in,
                              void* d_out, int out_size)
{
    const float* audio = (const float*)d_in[0];   // (2,250,1,1024) = 512000 f32
    const float* f0    = (const float*)d_in[1];   // (2,250,1)      = 500 f32

    const int frames = in_sizes[1];               // 500

    float* out_hd  = (float*)d_out;               // (frames, 64)
    float* out_amp = (float*)d_out + (size_t)frames * NH;  // (frames,)

    morlet_kernel<<<frames, THREADS>>>(audio, f0, out_hd, out_amp);
}